// round 5
// baseline (speedup 1.0000x reference)
#include <cuda_runtime.h>

#define NUM_GRAPHS 1024
#define TPB 128

// Scratch (device globals — no allocations allowed)
__device__ float g_S[NUM_GRAPHS * 3];   // sum q_i * r_i per graph
__device__ float g_R[NUM_GRAPHS * 3];   // sum r_i per graph
__device__ float g_Q[NUM_GRAPHS];       // sum q_i per graph
__device__ int   g_done = 0;            // last-block ticket (reset by last block)

// ---------------------------------------------------------------------------
// Single fused kernel, one block of 128 per graph.
//   prologue: dtype-detect + two cooperative 65-ary searches (4 rounds)
//   body:     float4-vectorized stream (4 LDG.128 per 4 nodes), x2 unroll
//   epilogue: block reduce; last block finalizes out = S - mean(q)*R
// ---------------------------------------------------------------------------
__global__ __launch_bounds__(TPB, 8) void polar_fused_kernel(
    const float* __restrict__ pos,       // [N,3]
    const float* __restrict__ q,         // [N]
    const void*  __restrict__ batch_raw, // [N] int32 or int64, sorted
    float*       __restrict__ out,       // [1024,3]
    int n, float inv_n)
{
    const int tid = threadIdx.x;
    const int g   = blockIdx.x;

    __shared__ int   sh_is64;
    __shared__ int   sh_lo[2], sh_hi[2];
    __shared__ int   sh_last;
    __shared__ float sh[4][7];
    __shared__ float sh_sumq;

    const int* b32 = (const int*)batch_raw;

    // --- dtype detect: int64 viewed as int32 words alternates value,0 near the
    //     tail (decreasing adjacent pairs); sorted int32 is nondecreasing.
    if (tid < 32) {
        int w = n - 34 + tid;
        int dec = (b32[w + 1] < b32[w]) ? 1 : 0;
        unsigned m = __ballot_sync(0xFFFFFFFFu, dec);
        if (tid == 0) sh_is64 = (m != 0u);
    }
    if (tid == 0) { sh_lo[0] = 0; sh_hi[0] = n; sh_lo[1] = 0; sh_hi[1] = n; }
    __syncthreads();
    const int is64 = sh_is64;

    // --- cooperative 65-ary lower_bound: group0 -> g, group1 -> g+1.
    //     64 probes/round; sizes 8.4M -> 129k -> 1986 -> 31 -> resolved (4 rds).
    {
        const int grp = tid >> 6;            // 0 or 1
        const int t   = tid & 63;
        const int target = g + grp;
        #pragma unroll
        for (int r = 0; r < 4; ++r) {
            int lo = sh_lo[grp], hi = sh_hi[grp];
            int size = hi - lo;
            int p = -1, pred = 0;
            if (size > 0) {
                p = lo + (int)(((long long)size * (t + 1)) / 65);
                if (p >= hi) p = hi - 1;
                int v = is64 ? b32[2 * p] : b32[p];  // labels are small nonneg
                pred = (v < target);
            }
            __syncthreads();
            if (size > 0) {
                if (pred) atomicMax(&sh_lo[grp], p + 1);
                else      atomicMin(&sh_hi[grp], p);
            }
            __syncthreads();
        }
    }
    const int start = sh_lo[0];
    const int end   = sh_lo[1];

    float sx = 0.f, sy = 0.f, sz = 0.f;
    float rx = 0.f, ry = 0.f, rz = 0.f;
    float qs = 0.f;

    // --- alignment split: vectorized interior covers node groups of 4
    int a = (start + 3) & ~3; if (a > end) a = end;
    int b = end & ~3;         if (b < a)   b = a;

    const float3* __restrict__ pos3 = (const float3*)pos;
    // scalar head (<4 nodes)
    for (int i = start + tid; i < a; i += TPB) {
        float  qi = q[i]; float3 p = pos3[i];
        sx = fmaf(qi, p.x, sx); sy = fmaf(qi, p.y, sy); sz = fmaf(qi, p.z, sz);
        rx += p.x; ry += p.y; rz += p.z; qs += qi;
    }
    // scalar tail (<4 nodes)
    for (int i = b + tid; i < end; i += TPB) {
        float  qi = q[i]; float3 p = pos3[i];
        sx = fmaf(qi, p.x, sx); sy = fmaf(qi, p.y, sy); sz = fmaf(qi, p.z, sz);
        rx += p.x; ry += p.y; rz += p.z; qs += qi;
    }

    // vectorized interior: group gi covers nodes [4gi, 4gi+4)
    const float4* __restrict__ pos4 = (const float4*)pos;
    const float4* __restrict__ q4p  = (const float4*)q;
    int gi   = (a >> 2) + tid;
    int gEnd = (b >> 2);

#define ACC_GROUP(V0, V1, V2, QV)                                            \
    do {                                                                     \
        sx = fmaf((QV).x, (V0).x, sx); sx = fmaf((QV).y, (V0).w, sx);        \
        sx = fmaf((QV).z, (V1).z, sx); sx = fmaf((QV).w, (V2).y, sx);        \
        sy = fmaf((QV).x, (V0).y, sy); sy = fmaf((QV).y, (V1).x, sy);        \
        sy = fmaf((QV).z, (V1).w, sy); sy = fmaf((QV).w, (V2).z, sy);        \
        sz = fmaf((QV).x, (V0).z, sz); sz = fmaf((QV).y, (V1).y, sz);        \
        sz = fmaf((QV).z, (V2).x, sz); sz = fmaf((QV).w, (V2).w, sz);        \
        rx += ((V0).x + (V0).w) + ((V1).z + (V2).y);                         \
        ry += ((V0).y + (V1).x) + ((V1).w + (V2).z);                         \
        rz += ((V0).z + (V1).y) + ((V2).x + (V2).w);                         \
        qs += ((QV).x + (QV).y) + ((QV).z + (QV).w);                         \
    } while (0)

    for (; gi + TPB < gEnd; gi += 2 * TPB) {
        int g2 = gi + TPB;
        float4 a0 = pos4[3 * gi + 0];
        float4 a1 = pos4[3 * gi + 1];
        float4 a2 = pos4[3 * gi + 2];
        float4 qa = q4p[gi];
        float4 c0 = pos4[3 * g2 + 0];
        float4 c1 = pos4[3 * g2 + 1];
        float4 c2 = pos4[3 * g2 + 2];
        float4 qc = q4p[g2];
        ACC_GROUP(a0, a1, a2, qa);
        ACC_GROUP(c0, c1, c2, qc);
    }
    for (; gi < gEnd; gi += TPB) {
        float4 a0 = pos4[3 * gi + 0];
        float4 a1 = pos4[3 * gi + 1];
        float4 a2 = pos4[3 * gi + 2];
        float4 qa = q4p[gi];
        ACC_GROUP(a0, a1, a2, qa);
    }
#undef ACC_GROUP

    // --- block reduction of 7 floats (4 warps)
    const unsigned FULL = 0xFFFFFFFFu;
    #pragma unroll
    for (int off = 16; off > 0; off >>= 1) {
        sx += __shfl_down_sync(FULL, sx, off);
        sy += __shfl_down_sync(FULL, sy, off);
        sz += __shfl_down_sync(FULL, sz, off);
        rx += __shfl_down_sync(FULL, rx, off);
        ry += __shfl_down_sync(FULL, ry, off);
        rz += __shfl_down_sync(FULL, rz, off);
        qs += __shfl_down_sync(FULL, qs, off);
    }
    int wid = tid >> 5, lid = tid & 31;
    if (lid == 0) {
        sh[wid][0] = sx; sh[wid][1] = sy; sh[wid][2] = sz;
        sh[wid][3] = rx; sh[wid][4] = ry; sh[wid][5] = rz;
        sh[wid][6] = qs;
    }
    __syncthreads();
    if (tid == 0) {
        float v0 = 0, v1 = 0, v2 = 0, v3 = 0, v4 = 0, v5 = 0, v6 = 0;
        #pragma unroll
        for (int w = 0; w < TPB / 32; ++w) {
            v0 += sh[w][0]; v1 += sh[w][1]; v2 += sh[w][2];
            v3 += sh[w][3]; v4 += sh[w][4]; v5 += sh[w][5];
            v6 += sh[w][6];
        }
        g_S[3 * g + 0] = v0; g_S[3 * g + 1] = v1; g_S[3 * g + 2] = v2;
        g_R[3 * g + 0] = v3; g_R[3 * g + 1] = v4; g_R[3 * g + 2] = v5;
        g_Q[g] = v6;
        __threadfence();
        int ticket = atomicAdd(&g_done, 1);
        sh_last = (ticket == (int)gridDim.x - 1);
    }
    __syncthreads();

    // --- last block: finalize out = S - mean(q) * R, reset ticket
    if (sh_last) {
        __threadfence();
        float s = 0.f;
        for (int k = tid; k < NUM_GRAPHS; k += TPB) s += g_Q[k];
        #pragma unroll
        for (int off = 16; off > 0; off >>= 1)
            s += __shfl_down_sync(FULL, s, off);
        if (lid == 0) sh[wid][0] = s;
        __syncthreads();
        if (tid == 0) {
            float t = 0.f;
            #pragma unroll
            for (int w = 0; w < TPB / 32; ++w) t += sh[w][0];
            sh_sumq = t;
            g_done = 0;                       // reset for graph replay
        }
        __syncthreads();
        float mean = sh_sumq * inv_n;
        for (int k = tid; k < NUM_GRAPHS * 3; k += TPB)
            out[k] = fmaf(-mean, g_R[k], g_S[k]);
    }
}

extern "C" void kernel_launch(void* const* d_in, const int* in_sizes, int n_in,
                              void* d_out, int out_size) {
    const float* pos   = (const float*)d_in[0];   // [N,3] float32
    const float* q     = (const float*)d_in[1];   // [N]   float32
    const void*  batch = (const void*)d_in[2];    // [N]   int32/int64 sorted
    float*       out   = (float*)d_out;           // [1024,3] float32
    int n = in_sizes[1];

    polar_fused_kernel<<<NUM_GRAPHS, TPB>>>(pos, q, batch, out, n, 1.0f / (float)n);
}

// round 6
// speedup vs baseline: 1.0585x; 1.0585x over previous
#include <cuda_runtime.h>
#include <cstdint>

#define NUM_GRAPHS 1024
#define TPB 256
#define GPC 240                       // groups (of 4 nodes) per chunk = 960 nodes
#define POS_CHUNK_B (GPC * 48)        // 11520
#define Q_CHUNK_B   (GPC * 16)       // 3840
#define NSTAGES 2

// Scratch (device globals — no allocations allowed)
__device__ float g_S[NUM_GRAPHS * 3];
__device__ float g_R[NUM_GRAPHS * 3];
__device__ float g_Q[NUM_GRAPHS];
__device__ int   g_done = 0;

// ---------------------------------------------------------------------------
// PTX helpers
// ---------------------------------------------------------------------------
__device__ __forceinline__ uint32_t smem_u32(const void* p) {
    uint32_t a;
    asm("{ .reg .u64 t; cvta.to.shared.u64 t, %1; cvt.u32.u64 %0, t; }"
        : "=r"(a) : "l"(p));
    return a;
}
__device__ __forceinline__ void mbar_init(uint32_t mbar, uint32_t cnt) {
    asm volatile("mbarrier.init.shared.b64 [%0], %1;" :: "r"(mbar), "r"(cnt) : "memory");
}
__device__ __forceinline__ void mbar_expect_tx(uint32_t mbar, uint32_t bytes) {
    asm volatile("mbarrier.arrive.expect_tx.shared.b64 _, [%0], %1;"
                 :: "r"(mbar), "r"(bytes) : "memory");
}
__device__ __forceinline__ void bulk_ld(uint32_t dst, const void* src,
                                        uint32_t bytes, uint32_t mbar) {
    asm volatile(
        "cp.async.bulk.shared::cta.global.mbarrier::complete_tx::bytes "
        "[%0], [%1], %2, [%3];"
        :: "r"(dst), "l"(src), "r"(bytes), "r"(mbar) : "memory");
}
__device__ __forceinline__ void mbar_wait(uint32_t mbar, uint32_t parity) {
    uint32_t done;
    asm volatile(
        "{\n\t.reg .pred p;\n\t"
        "mbarrier.try_wait.parity.acquire.cta.shared::cta.b64 p, [%1], %2;\n\t"
        "selp.b32 %0, 1, 0, p;\n\t}"
        : "=r"(done) : "r"(mbar), "r"(parity) : "memory");
    if (!done) {
        asm volatile(
            "{\n\t.reg .pred P1;\n\t"
            "WL_%=:\n\t"
            "mbarrier.try_wait.parity.acquire.cta.shared::cta.b64 P1, [%0], %1, 0x989680;\n\t"
            "@P1 bra.uni WD_%=;\n\t"
            "bra.uni WL_%=;\n\t"
            "WD_%=:\n\t}"
            :: "r"(mbar), "r"(parity) : "memory");
    }
}

// ---------------------------------------------------------------------------
// Fused kernel: one block of 256 per graph.
//   prologue : dtype detect + two cooperative 129-ary searches (4 rounds)
//   body     : TMA double-buffered stream of the segment interior
//   epilogue : block reduce; last block finalizes out = S - mean(q)*R
// ---------------------------------------------------------------------------
__global__ __launch_bounds__(TPB) void polar_tma_kernel(
    const float* __restrict__ pos,       // [N,3]
    const float* __restrict__ q,         // [N]
    const void*  __restrict__ batch_raw, // [N] int32 or int64, sorted
    float*       __restrict__ out,       // [1024,3]
    int n, float inv_n)
{
    const int tid = threadIdx.x;
    const int g   = blockIdx.x;

    __shared__ __align__(128) float sm_pos[NSTAGES][POS_CHUNK_B / 4];
    __shared__ __align__(128) float sm_q[NSTAGES][Q_CHUNK_B / 4];
    __shared__ __align__(8)   unsigned long long sm_mbar[NSTAGES];
    __shared__ int   sh_is64;
    __shared__ int   sh_lo[2], sh_hi[2];
    __shared__ int   sh_last;
    __shared__ float sh[8][7];
    __shared__ float sh_sumq;

    const int* b32 = (const int*)batch_raw;

    // --- mbarrier init + dtype detect ---
    if (tid == 0) {
        mbar_init(smem_u32(&sm_mbar[0]), 1);
        mbar_init(smem_u32(&sm_mbar[1]), 1);
        sh_lo[0] = 0; sh_hi[0] = n; sh_lo[1] = 0; sh_hi[1] = n;
    }
    if (tid < 32) {
        int w = n - 34 + tid;
        int dec = (b32[w + 1] < b32[w]) ? 1 : 0;
        unsigned m = __ballot_sync(0xFFFFFFFFu, dec);
        if (tid == 0) sh_is64 = (m != 0u);
    }
    __syncthreads();
    const int is64 = sh_is64;

    // --- cooperative 129-ary lower_bound: group0 -> g, group1 -> g+1 ---
    {
        const int grp = tid >> 7;
        const int t   = tid & 127;
        const int target = g + grp;
        #pragma unroll
        for (int r = 0; r < 4; ++r) {
            int lo = sh_lo[grp], hi = sh_hi[grp];
            int size = hi - lo;
            int p = -1, pred = 0;
            if (size > 0) {
                p = lo + (int)(((long long)size * (t + 1)) / 129);
                if (p >= hi) p = hi - 1;
                int v = is64 ? b32[2 * p] : b32[p];
                pred = (v < target);
            }
            __syncthreads();
            if (size > 0) {
                if (pred) atomicMax(&sh_lo[grp], p + 1);
                else      atomicMin(&sh_hi[grp], p);
            }
            __syncthreads();
        }
    }
    const int start = sh_lo[0];
    const int end   = sh_lo[1];

    // --- split: 4-node aligned interior + scalar head/tail ---
    int a = (start + 3) & ~3; if (a > end) a = end;
    int b = end & ~3;         if (b < a)   b = a;
    const int aG = a >> 2, bG = b >> 2;
    const int totG = bG - aG;
    const int nChunks = (totG + GPC - 1) / GPC;

    const char* posB = (const char*)pos;
    const char* qB   = (const char*)q;

    // --- prologue: issue first NSTAGES chunks ---
    if (tid == 0) {
        #pragma unroll
        for (int c = 0; c < NSTAGES; ++c) {
            if (c < nChunks) {
                int gb  = aG + c * GPC;
                int cnt = min(GPC, bG - gb);
                uint32_t mb = smem_u32(&sm_mbar[c]);
                mbar_expect_tx(mb, (uint32_t)(cnt * 64));
                bulk_ld(smem_u32(&sm_pos[c][0]), posB + (size_t)gb * 48,
                        (uint32_t)(cnt * 48), mb);
                bulk_ld(smem_u32(&sm_q[c][0]), qB + (size_t)gb * 16,
                        (uint32_t)(cnt * 16), mb);
            }
        }
    }

    float sx = 0.f, sy = 0.f, sz = 0.f;
    float rx = 0.f, ry = 0.f, rz = 0.f;
    float qs = 0.f;

    // --- scalar head/tail (overlap with in-flight TMA) ---
    const float3* __restrict__ pos3 = (const float3*)pos;
    for (int i = start + tid; i < a; i += TPB) {
        float  qi = q[i]; float3 p = pos3[i];
        sx = fmaf(qi, p.x, sx); sy = fmaf(qi, p.y, sy); sz = fmaf(qi, p.z, sz);
        rx += p.x; ry += p.y; rz += p.z; qs += qi;
    }
    for (int i = b + tid; i < end; i += TPB) {
        float  qi = q[i]; float3 p = pos3[i];
        sx = fmaf(qi, p.x, sx); sy = fmaf(qi, p.y, sy); sz = fmaf(qi, p.z, sz);
        rx += p.x; ry += p.y; rz += p.z; qs += qi;
    }

    // --- pipelined interior ---
    for (int k = 0; k < nChunks; ++k) {
        const int s   = k & 1;
        const int par = (k >> 1) & 1;
        const int gb  = aG + k * GPC;
        const int cnt = min(GPC, bG - gb);

        mbar_wait(smem_u32(&sm_mbar[s]), par);

        if (tid < cnt) {
            const float4* p4 = (const float4*)&sm_pos[s][0];
            const float4* q4 = (const float4*)&sm_q[s][0];
            float4 v0 = p4[3 * tid + 0];
            float4 v1 = p4[3 * tid + 1];
            float4 v2 = p4[3 * tid + 2];
            float4 qv = q4[tid];
            sx = fmaf(qv.x, v0.x, sx); sx = fmaf(qv.y, v0.w, sx);
            sx = fmaf(qv.z, v1.z, sx); sx = fmaf(qv.w, v2.y, sx);
            sy = fmaf(qv.x, v0.y, sy); sy = fmaf(qv.y, v1.x, sy);
            sy = fmaf(qv.z, v1.w, sy); sy = fmaf(qv.w, v2.z, sy);
            sz = fmaf(qv.x, v0.z, sz); sz = fmaf(qv.y, v1.y, sz);
            sz = fmaf(qv.z, v2.x, sz); sz = fmaf(qv.w, v2.w, sz);
            rx += (v0.x + v0.w) + (v1.z + v2.y);
            ry += (v0.y + v1.x) + (v1.w + v2.z);
            rz += (v0.z + v1.y) + (v2.x + v2.w);
            qs += (qv.x + qv.y) + (qv.z + qv.w);
        }
        __syncthreads();   // everyone done with stage s

        if (tid == 0 && k + NSTAGES < nChunks) {
            int gb2  = aG + (k + NSTAGES) * GPC;
            int cnt2 = min(GPC, bG - gb2);
            uint32_t mb = smem_u32(&sm_mbar[s]);
            mbar_expect_tx(mb, (uint32_t)(cnt2 * 64));
            bulk_ld(smem_u32(&sm_pos[s][0]), posB + (size_t)gb2 * 48,
                    (uint32_t)(cnt2 * 48), mb);
            bulk_ld(smem_u32(&sm_q[s][0]), qB + (size_t)gb2 * 16,
                    (uint32_t)(cnt2 * 16), mb);
        }
    }

    // --- block reduction of 7 floats (8 warps) ---
    const unsigned FULL = 0xFFFFFFFFu;
    #pragma unroll
    for (int off = 16; off > 0; off >>= 1) {
        sx += __shfl_down_sync(FULL, sx, off);
        sy += __shfl_down_sync(FULL, sy, off);
        sz += __shfl_down_sync(FULL, sz, off);
        rx += __shfl_down_sync(FULL, rx, off);
        ry += __shfl_down_sync(FULL, ry, off);
        rz += __shfl_down_sync(FULL, rz, off);
        qs += __shfl_down_sync(FULL, qs, off);
    }
    int wid = tid >> 5, lid = tid & 31;
    if (lid == 0) {
        sh[wid][0] = sx; sh[wid][1] = sy; sh[wid][2] = sz;
        sh[wid][3] = rx; sh[wid][4] = ry; sh[wid][5] = rz;
        sh[wid][6] = qs;
    }
    __syncthreads();
    if (tid == 0) {
        float v0 = 0, v1 = 0, v2 = 0, v3 = 0, v4 = 0, v5 = 0, v6 = 0;
        #pragma unroll
        for (int w = 0; w < TPB / 32; ++w) {
            v0 += sh[w][0]; v1 += sh[w][1]; v2 += sh[w][2];
            v3 += sh[w][3]; v4 += sh[w][4]; v5 += sh[w][5];
            v6 += sh[w][6];
        }
        g_S[3 * g + 0] = v0; g_S[3 * g + 1] = v1; g_S[3 * g + 2] = v2;
        g_R[3 * g + 0] = v3; g_R[3 * g + 1] = v4; g_R[3 * g + 2] = v5;
        g_Q[g] = v6;
        __threadfence();
        int ticket = atomicAdd(&g_done, 1);
        sh_last = (ticket == (int)gridDim.x - 1);
    }
    __syncthreads();

    // --- last block finalizes ---
    if (sh_last) {
        __threadfence();
        float s = 0.f;
        for (int k = tid; k < NUM_GRAPHS; k += TPB) s += g_Q[k];
        #pragma unroll
        for (int off = 16; off > 0; off >>= 1)
            s += __shfl_down_sync(FULL, s, off);
        if (lid == 0) sh[wid][0] = s;
        __syncthreads();
        if (tid == 0) {
            float t = 0.f;
            #pragma unroll
            for (int w = 0; w < TPB / 32; ++w) t += sh[w][0];
            sh_sumq = t;
            g_done = 0;
        }
        __syncthreads();
        float mean = sh_sumq * inv_n;
        for (int k = tid; k < NUM_GRAPHS * 3; k += TPB)
            out[k] = fmaf(-mean, g_R[k], g_S[k]);
    }
}

extern "C" void kernel_launch(void* const* d_in, const int* in_sizes, int n_in,
                              void* d_out, int out_size) {
    const float* pos   = (const float*)d_in[0];   // [N,3] float32
    const float* q     = (const float*)d_in[1];   // [N]   float32
    const void*  batch = (const void*)d_in[2];    // [N]   int32/int64 sorted
    float*       out   = (float*)d_out;           // [1024,3] float32
    int n = in_sizes[1];

    polar_tma_kernel<<<NUM_GRAPHS, TPB>>>(pos, q, batch, out, n, 1.0f / (float)n);
}